// round 16
// baseline (speedup 1.0000x reference)
#include <cuda_runtime.h>
#include <cuda_fp16.h>
#include <math.h>
#include <stdint.h>

#define B_   4
#define L_   2048
#define H_   2048
#define NH_  16
#define HD_  128
#define M_   8192           // B*L
#define N1_  6144           // 3*H

// ================= scratch ===================================================
__device__ __half g_qkv[(size_t)M_ * N1_];    // fp16 qkv
__device__ __half g_xh[(size_t)M_ * H_];
__device__ __half g_wq_h[(size_t)N1_ * H_];   // Wqkv^T [6144][2048]
__device__ __half g_wf_h[(size_t)H_ * H_];    // Wfc2^T [2048][2048]
__device__ __half g_yh[(size_t)M_ * H_];
__device__ __half g_qh[(size_t)M_ * H_];      // [b,h,l,d]
__device__ __half g_kh[(size_t)M_ * H_];
__device__ __half g_vh[(size_t)M_ * H_];

// ================= small helpers ============================================
__device__ __forceinline__ uint32_t smem_u32(const void* p) {
    uint32_t a;
    asm("{ .reg .u64 t; cvta.to.shared.u64 t, %1; cvt.u32.u64 %0, t; }"
        : "=r"(a) : "l"(p));
    return a;
}
__device__ __forceinline__ void ldsm4(uint32_t* r, uint32_t addr) {
    asm volatile("ldmatrix.sync.aligned.m8n8.x4.shared.b16 {%0,%1,%2,%3}, [%4];"
        : "=r"(r[0]), "=r"(r[1]), "=r"(r[2]), "=r"(r[3]) : "r"(addr));
}
__device__ __forceinline__ void ldsm4t(uint32_t* r, uint32_t addr) {
    asm volatile("ldmatrix.sync.aligned.m8n8.x4.trans.shared.b16 {%0,%1,%2,%3}, [%4];"
        : "=r"(r[0]), "=r"(r[1]), "=r"(r[2]), "=r"(r[3]) : "r"(addr));
}
__device__ __forceinline__ void mma16816(float* c, const uint32_t* a, const uint32_t* b) {
    asm volatile("mma.sync.aligned.m16n8k16.row.col.f32.f16.f16.f32 "
        "{%0,%1,%2,%3}, {%4,%5,%6,%7}, {%8,%9}, {%0,%1,%2,%3};"
        : "+f"(c[0]), "+f"(c[1]), "+f"(c[2]), "+f"(c[3])
        : "r"(a[0]), "r"(a[1]), "r"(a[2]), "r"(a[3]), "r"(b[0]), "r"(b[1]));
}
__device__ __forceinline__ void cp_async16(uint32_t saddr, const void* gaddr) {
    asm volatile("cp.async.cg.shared.global [%0], [%1], 16;"
                 :: "r"(saddr), "l"(gaddr));
}
#define CP_COMMIT() asm volatile("cp.async.commit_group;")
#define CP_WAIT(N)  asm volatile("cp.async.wait_group %0;" :: "n"(N))

// ================= conversion kernels =======================================
__global__ __launch_bounds__(256) void cvt_fp16(
    const float* __restrict__ X, __half* __restrict__ Xh, int n4)
{
    int i = blockIdx.x * 256 + threadIdx.x;
    if (i >= n4) return;
    float4 v = *(const float4*)(X + (size_t)i * 4);
    __half2 a = __floats2half2_rn(v.x, v.y);
    __half2 b = __floats2half2_rn(v.z, v.w);
    uint2 o = make_uint2(*(uint32_t*)&a, *(uint32_t*)&b);
    *(uint2*)(Xh + (size_t)i * 4) = o;
}

// W [K x N] fp32 -> Wt [N x K] fp16
__global__ __launch_bounds__(256) void transpose_h(
    const float* __restrict__ W, __half* __restrict__ Th, int K, int N)
{
    __shared__ float t[32][33];
    int n0 = blockIdx.x * 32, k0 = blockIdx.y * 32;
    int tx = threadIdx.x, ty = threadIdx.y;
#pragma unroll
    for (int i = ty; i < 32; i += 8)
        t[i][tx] = W[(size_t)(k0 + i) * N + n0 + tx];
    __syncthreads();
#pragma unroll
    for (int i = ty; i < 32; i += 8)
        Th[(size_t)(n0 + i) * K + k0 + tx] = __float2half_rn(t[tx][i]);
}

// ================= fp16 warp-MMA GEMM (K-step 64, 3-stage ring) =============
// C = Ah @ Bh^T + bias (opt silu). Block 128x128, 4 warps (warp 64x64).
// Row stride 144 B (36 words == 4 mod 32: ldsm conflict-free). 2 CTAs/SM.
#define GT_RS      144
#define GT_TILE_B  (128 * GT_RS)              // 18432 B
#define GT_STAGE_B (2 * GT_TILE_B)            // 36864 B
#define GEMM_SMEM  (3 * GT_STAGE_B)           // 110592 B

template<int SILU, int OUTH>
__global__ __launch_bounds__(128, 2) void gemm_mma(
    const __half* __restrict__ Ah, const __half* __restrict__ Bh,
    const float* __restrict__ bias, void* __restrict__ Cv,
    int Ng, int Kg)
{
    extern __shared__ char smem[];
    const uint32_t sb = smem_u32(smem);
    const int tid  = threadIdx.x;
    const int lane = tid & 31;
    const int wid  = tid >> 5;          // 0..3
    const int wm   = wid & 1;
    const int wn   = wid >> 1;
    const int m0 = blockIdx.y * 128;
    const int n0 = blockIdx.x * 128;

    const __half* gsrc[2] = { Ah + (size_t)m0 * Kg, Bh + (size_t)n0 * Kg };

    const int a_row = ((lane >> 3) & 1) * 8 + (lane & 7);
    const int a_kof = (lane >> 4) * 8;
    const int b_row = (lane >> 4) * 8 + (lane & 7);
    const int b_kof = ((lane >> 3) & 1) * 8;

    float acc[4][8][4];
#pragma unroll
    for (int i = 0; i < 4; i++)
#pragma unroll
        for (int j = 0; j < 8; j++)
#pragma unroll
            for (int k = 0; k < 4; k++) acc[i][j][k] = 0.f;

    const int nst = Kg >> 6;            // 64-wide K steps

    auto load_stage = [&](int s) {
        const uint32_t stb = sb + (s % 3) * GT_STAGE_B;
        const int k0 = s << 6;
#pragma unroll
        for (int j = 0; j < 16; j++) {
            int c = tid + j * 128;          // 0..2047
            int tile = c >> 10;             // 0..1
            int idx = c & 1023;
            int r = idx >> 3, q = idx & 7;
            uint32_t sa = stb + tile * GT_TILE_B + r * GT_RS + q * 16;
            cp_async16(sa, gsrc[tile] + (size_t)r * Kg + k0 + q * 8);
        }
        CP_COMMIT();
    };

    load_stage(0);
    load_stage(1);

    for (int i = 0; i < nst; i++) {
        CP_WAIT(1);
        __syncthreads();
        if (i + 2 < nst) load_stage(i + 2);

        const uint32_t stb = sb + (i % 3) * GT_STAGE_B;
        const uint32_t sA  = stb;
        const uint32_t sB  = stb + GT_TILE_B;

#pragma unroll
        for (int kk = 0; kk < 4; kk++) {
            const int kb = kk * 16;
            uint32_t ah[4][4], bh[4][4];
#pragma unroll
            for (int mi = 0; mi < 4; mi++) {
                uint32_t ro = (uint32_t)((wm * 64 + mi * 16 + a_row) * GT_RS
                                         + (kb + a_kof) * 2);
                ldsm4(ah[mi], sA + ro);
            }
#pragma unroll
            for (int nj = 0; nj < 4; nj++) {
                uint32_t ro = (uint32_t)((wn * 64 + nj * 16 + b_row) * GT_RS
                                         + (kb + b_kof) * 2);
                ldsm4(bh[nj], sB + ro);
            }
#pragma unroll
            for (int mi = 0; mi < 4; mi++)
#pragma unroll
                for (int ni = 0; ni < 8; ni++) {
                    const uint32_t* bf = &bh[ni >> 1][2 * (ni & 1)];
                    mma16816(acc[mi][ni], ah[mi], bf);
                }
        }
        __syncthreads();
    }

    const int g = lane >> 2, t4 = lane & 3;
#pragma unroll
    for (int mi = 0; mi < 4; mi++) {
#pragma unroll
        for (int ni = 0; ni < 8; ni++) {
            int row0 = m0 + wm * 64 + mi * 16 + g;
            int col  = n0 + wn * 64 + ni * 8 + t4 * 2;
            float b0 = bias[col], b1 = bias[col + 1];
            float z0 = acc[mi][ni][0] + b0, z1 = acc[mi][ni][1] + b1;
            float z2 = acc[mi][ni][2] + b0, z3 = acc[mi][ni][3] + b1;
            if (SILU) {
                z0 = z0 / (1.f + expf(-z0)); z1 = z1 / (1.f + expf(-z1));
                z2 = z2 / (1.f + expf(-z2)); z3 = z3 / (1.f + expf(-z3));
            }
            if (OUTH) {
                __half* C = (__half*)Cv;
                *(__half2*)&C[(size_t)row0 * Ng + col] = __floats2half2_rn(z0, z1);
                *(__half2*)&C[(size_t)(row0 + 8) * Ng + col] = __floats2half2_rn(z2, z3);
            } else {
                float* C = (float*)Cv;
                *(float2*)&C[(size_t)row0 * Ng + col]       = make_float2(z0, z1);
                *(float2*)&C[(size_t)(row0 + 8) * Ng + col] = make_float2(z2, z3);
            }
        }
    }
}

// ================= RoPE + head-scatter (fp16 in) ============================
__global__ __launch_bounds__(256) void rope_scatter(
    const float* __restrict__ cosb, const float* __restrict__ sinb,
    const __half* __restrict__ qkv,
    __half* __restrict__ Qh,
    __half* __restrict__ Kh,
    __half* __restrict__ Vh)
{
    __shared__ __half row[6144];
    __shared__ float cr[1024];
    __shared__ float sr[1024];

    const int m = blockIdx.x;
    const int b = m >> 11;
    const int l = m & 2047;
    const __half* src = qkv + (size_t)m * 6144;

    for (int i = threadIdx.x; i < 768; i += 256)
        *(uint4*)&row[i * 8] = *(const uint4*)&src[i * 8];
    {
        int i4 = threadIdx.x;
        *(float4*)&cr[i4 * 4] = *(const float4*)&cosb[(size_t)l * 1024 + i4 * 4];
        *(float4*)&sr[i4 * 4] = *(const float4*)&sinb[(size_t)l * 1024 + i4 * 4];
    }
    __syncthreads();

    const float scale = 0.08838834764831845f;
#pragma unroll
    for (int it = 0; it < 4; it++) {
        int u = it * 256 + threadIdx.x;
        int h = u >> 6;
        int dlo = u & 63;
        int jj = dlo * 16 + h;
        float c = cr[jj], s = sr[jj];
        float q1 = __half2float(row[jj]);
        float q2 = __half2float(row[jj + 1024]);
        float k1 = __half2float(row[2048 + jj]);
        float k2 = __half2float(row[3072 + jj]);
        size_t base = (((size_t)b * 16 + h) * 2048 + l) * 128;

        Qh[base + dlo]      = __float2half_rn(( q1 * c + q2 * s) * scale);
        Qh[base + dlo + 64] = __float2half_rn((-q1 * s + q2 * c) * scale);
        Kh[base + dlo]      = __float2half_rn( k1 * c + k2 * s);
        Kh[base + dlo + 64] = __float2half_rn(-k1 * s + k2 * c);
        Vh[base + dlo]      = row[4096 + jj];
        Vh[base + dlo + 64] = row[4096 + jj + 1024];
    }
}

// ================= causal flash attention (HMMA, pipelined loads) ===========
// Tiles: Q, K0, K1, V (4 x 64x128 padded) = 69632 B -> 3 CTAs/SM.
// K double-buffered (prefetch during compute); V wait deferred past S+softmax.
#define AT_SW 136
#define AT_TILE_H (64 * AT_SW)
#define ATT_SMEM (4 * AT_TILE_H * 2)            // 69632 B

__global__ __launch_bounds__(128) void attn_mma(
    const __half* __restrict__ Qhg,
    const __half* __restrict__ Khg,
    const __half* __restrict__ Vhg,
    __half* __restrict__ Yh)
{
    extern __shared__ __half smh[];
    __half* sQh = smh;
    __half* sK0 = sQh + AT_TILE_H;
    __half* sK1 = sK0 + AT_TILE_H;
    __half* sVh = sK1 + AT_TILE_H;

    const uint32_t uQh = smem_u32(sQh);
    const uint32_t uK[2] = {smem_u32(sK0), smem_u32(sK1)};
    const uint32_t uVh = smem_u32(sVh);

    const int tid = threadIdx.x;
    const int lane = tid & 31;
    const int w = tid >> 5;
    const int g = lane >> 2, t4 = lane & 3;
    const int qt = gridDim.x - 1 - blockIdx.x;     // heavy blocks first
    const int bh = blockIdx.y;
    const int b = bh >> 4, h = bh & 15;
    const int q0 = qt * 64;
    const size_t hb = (size_t)bh * L_ * HD_;

    const int lrow = lane & 15;
    const int lcol8 = ((lane >> 4) << 3);

    const __half* Kg = Khg + hb;
    const __half* Vg = Vhg + hb;

    auto load_k = [&](int kt) {
        const int k0 = kt * 64;
        const uint32_t dst = uK[kt & 1];
#pragma unroll
        for (int j = 0; j < 8; j++) {
            int idx = tid + j * 128;
            int r = idx >> 4, ch = idx & 15;
            cp_async16(dst + (uint32_t)(r * AT_SW + ch * 8) * 2,
                       Kg + (size_t)(k0 + r) * 128 + ch * 8);
        }
    };
    auto load_v = [&](int kt) {
        const int k0 = kt * 64;
#pragma unroll
        for (int j = 0; j < 8; j++) {
            int idx = tid + j * 128;
            int r = idx >> 4, ch = idx & 15;
            cp_async16(uVh + (uint32_t)(r * AT_SW + ch * 8) * 2,
                       Vg + (size_t)(k0 + r) * 128 + ch * 8);
        }
    };

    // ---- prologue: [Q + K(0)] group, then [V(0)] group ----
    {
#pragma unroll
        for (int j = 0; j < 8; j++) {
            int idx = tid + j * 128;
            int r = idx >> 4, ch = idx & 15;
            cp_async16(uQh + (uint32_t)(r * AT_SW + ch * 8) * 2,
                       Qhg + hb + (size_t)(q0 + r) * 128 + ch * 8);
        }
        load_k(0);
        CP_COMMIT();
        load_v(0);
        CP_COMMIT();
    }

    float acc_o[16][4];
#pragma unroll
    for (int j = 0; j < 16; j++)
#pragma unroll
        for (int c = 0; c < 4; c++) acc_o[j][c] = 0.f;
    float mrow[2] = {-1e30f, -1e30f};
    float lrowv[2] = {0.f, 0.f};

    for (int kt = 0; kt <= qt; kt++) {
        // wait: K(kt) ready (V(kt) may still be in flight)
        CP_WAIT(1);
        __syncthreads();
        // prefetch K(kt+1) into the other K buffer
        if (kt < qt) load_k(kt + 1);
        CP_COMMIT();

        const uint32_t uKc = uK[kt & 1];

        // ---- S = Q K^T ----
        float acc_s[8][4];
#pragma unroll
        for (int j = 0; j < 8; j++)
#pragma unroll
            for (int c = 0; c < 4; c++) acc_s[j][c] = 0.f;

#pragma unroll
        for (int ks = 0; ks < 8; ks++) {
            const uint32_t aoff = (uint32_t)((w * 16 + lrow) * AT_SW + ks * 16 + lcol8) * 2;
            uint32_t aQ[4];
            ldsm4(aQ, uQh + aoff);
#pragma unroll
            for (int ng = 0; ng < 4; ng++) {
                const uint32_t boff =
                    (uint32_t)((ng * 16 + lrow) * AT_SW + ks * 16 + lcol8) * 2;
                uint32_t bK[4];
                ldsm4(bK, uKc + boff);
                uint32_t b0[2] = {bK[0], bK[2]}, b1[2] = {bK[1], bK[3]};
                mma16816(acc_s[2 * ng],     aQ, b0);
                mma16816(acc_s[2 * ng + 1], aQ, b1);
            }
        }

        // ---- causal mask on diagonal tile ----
        if (kt == qt) {
#pragma unroll
            for (int j = 0; j < 8; j++)
#pragma unroll
                for (int c = 0; c < 4; c++) {
                    int col = j * 8 + 2 * t4 + (c & 1);
                    int rowr = w * 16 + g + 8 * (c >> 1);
                    if (col > rowr) acc_s[j][c] = -1e30f;
                }
        }

        // ---- online softmax ----
        uint32_t ps[8][2];
#pragma unroll
        for (int rh = 0; rh < 2; rh++) {
            float mx = -1e30f;
#pragma unroll
            for (int j = 0; j < 8; j++)
                mx = fmaxf(mx, fmaxf(acc_s[j][2 * rh], acc_s[j][2 * rh + 1]));
            mx = fmaxf(mx, __shfl_xor_sync(0xffffffffu, mx, 1));
            mx = fmaxf(mx, __shfl_xor_sync(0xffffffffu, mx, 2));
            float mnew = fmaxf(mrow[rh], mx);
            float rs = 0.f;
#pragma unroll
            for (int j = 0; j < 8; j++) {
                float p0 = __expf(acc_s[j][2 * rh]     - mnew);
                float p1 = __expf(acc_s[j][2 * rh + 1] - mnew);
                rs += p0 + p1;
                __half2 hp = __floats2half2_rn(p0, p1);
                ps[j][rh] = *(uint32_t*)&hp;
            }
            rs += __shfl_xor_sync(0xffffffffu, rs, 1);
            rs += __shfl_xor_sync(0xffffffffu, rs, 2);
            float f = __expf(mrow[rh] - mnew);
            lrowv[rh] = lrowv[rh] * f + rs;
            mrow[rh] = mnew;
#pragma unroll
            for (int j = 0; j < 16; j++) {
                acc_o[j][2 * rh]     *= f;
                acc_o[j][2 * rh + 1] *= f;
            }
        }

        // wait: V(kt) ready (K(kt+1) still in flight)
        CP_WAIT(1);
        __syncthreads();

        // ---- O += P V ----
#pragma unroll
        for (int kk = 0; kk < 4; kk++) {
            uint32_t a[4] = {ps[2 * kk][0], ps[2 * kk][1],
                             ps[2 * kk + 1][0], ps[2 * kk + 1][1]};
#pragma unroll
            for (int nd = 0; nd < 8; nd++) {
                const uint32_t voff =
                    (uint32_t)((kk * 16 + lrow) * AT_SW + nd * 16 + lcol8) * 2;
                uint32_t vh[4];
                ldsm4t(vh, uVh + voff);
                mma16816(acc_o[2 * nd],     a, &vh[0]);
                mma16816(acc_o[2 * nd + 1], a, &vh[2]);
            }
        }

        // all warps done with V before next V load overwrites it
        __syncthreads();
        if (kt < qt) load_v(kt + 1);
        CP_COMMIT();
    }

    // ---- epilogue ----
#pragma unroll
    for (int rh = 0; rh < 2; rh++) {
        const int qi = q0 + w * 16 + g + 8 * rh;
        const float inv = 1.f / lrowv[rh];
        const size_t base = ((size_t)(b * L_ + qi)) * H_ + h * HD_;
#pragma unroll
        for (int j = 0; j < 16; j++) {
            __half2 hv = __floats2half2_rn(acc_o[j][2 * rh] * inv,
                                           acc_o[j][2 * rh + 1] * inv);
            *(__half2*)&Yh[base + j * 8 + 2 * t4] = hv;
        }
    }
}

// ================= launch ====================================================
extern "C" void kernel_launch(void* const* d_in, const int* in_sizes, int n_in,
                              void* d_out, int out_size)
{
    (void)in_sizes; (void)n_in; (void)out_size;
    const float* x    = (const float*)d_in[0];
    const float* Wqkv = (const float*)d_in[1];
    const float* bqkv = (const float*)d_in[2];
    const float* Wfc2 = (const float*)d_in[3];
    const float* bfc2 = (const float*)d_in[4];
    const float* cosb = (const float*)d_in[5];
    const float* sinb = (const float*)d_in[6];
    float* out = (float*)d_out;

    __half *qkv_p, *xh, *wqh, *wfh, *yh, *qh, *kh, *vh;
    cudaGetSymbolAddress((void**)&qkv_p, g_qkv);
    cudaGetSymbolAddress((void**)&xh, g_xh);
    cudaGetSymbolAddress((void**)&wqh, g_wq_h);
    cudaGetSymbolAddress((void**)&wfh, g_wf_h);
    cudaGetSymbolAddress((void**)&yh, g_yh);
    cudaGetSymbolAddress((void**)&qh, g_qh);
    cudaGetSymbolAddress((void**)&kh, g_kh);
    cudaGetSymbolAddress((void**)&vh, g_vh);

    cudaFuncSetAttribute(gemm_mma<0, 1>,
                         cudaFuncAttributeMaxDynamicSharedMemorySize, GEMM_SMEM);
    cudaFuncSetAttribute(gemm_mma<1, 0>,
                         cudaFuncAttributeMaxDynamicSharedMemorySize, GEMM_SMEM);
    cudaFuncSetAttribute(attn_mma,
                         cudaFuncAttributeMaxDynamicSharedMemorySize, ATT_SMEM);

    // input conversions
    cvt_fp16<<<(M_ * H_) / 1024, 256>>>(x, xh, (M_ * H_) / 4);
    transpose_h<<<dim3(N1_ / 32, H_ / 32), dim3(32, 8)>>>(Wqkv, wqh, H_, N1_);
    transpose_h<<<dim3(H_ / 32, H_ / 32), dim3(32, 8)>>>(Wfc2, wfh, H_, H_);

    // 1) qkv = x @ Wqkv + bqkv  (fp16 out)
    gemm_mma<0, 1><<<dim3(N1_ / 128, M_ / 128), 128, GEMM_SMEM>>>(
        xh, wqh, bqkv, qkv_p, N1_, H_);
    // 2) RoPE + head scatter
    rope_scatter<<<M_, 256>>>(cosb, sinb, qkv_p, qh, kh, vh);
    // 3) causal flash attention -> yh fp16
    attn_mma<<<dim3(32, 64), 128, ATT_SMEM>>>(qh, kh, vh, yh);
    // 4) out = silu(y @ Wfc2 + bfc2)  (fp32 out)
    gemm_mma<1, 0><<<dim3(H_ / 128, M_ / 128), 128, GEMM_SMEM>>>(
        yh, wfh, bfc2, out, H_, H_);
}

// round 17
// speedup vs baseline: 1.0641x; 1.0641x over previous
#include <cuda_runtime.h>
#include <cuda_fp16.h>
#include <math.h>
#include <stdint.h>

#define B_   4
#define L_   2048
#define H_   2048
#define NH_  16
#define HD_  128
#define M_   8192           // B*L
#define N1_  6144           // 3*H

// ================= scratch ===================================================
__device__ __half g_qkv[(size_t)M_ * N1_];    // fp16 qkv
__device__ __half g_xh[(size_t)M_ * H_];
__device__ __half g_wq_h[(size_t)N1_ * H_];   // Wqkv^T [6144][2048]
__device__ __half g_wf_h[(size_t)H_ * H_];    // Wfc2^T [2048][2048]
__device__ __half g_yh[(size_t)M_ * H_];
__device__ __half g_qh[(size_t)M_ * H_];      // [b,h,l,d]
__device__ __half g_kh[(size_t)M_ * H_];
__device__ __half g_vh[(size_t)M_ * H_];

// ================= small helpers ============================================
__device__ __forceinline__ uint32_t smem_u32(const void* p) {
    uint32_t a;
    asm("{ .reg .u64 t; cvta.to.shared.u64 t, %1; cvt.u32.u64 %0, t; }"
        : "=r"(a) : "l"(p));
    return a;
}
__device__ __forceinline__ void ldsm4(uint32_t* r, uint32_t addr) {
    asm volatile("ldmatrix.sync.aligned.m8n8.x4.shared.b16 {%0,%1,%2,%3}, [%4];"
        : "=r"(r[0]), "=r"(r[1]), "=r"(r[2]), "=r"(r[3]) : "r"(addr));
}
__device__ __forceinline__ void ldsm4t(uint32_t* r, uint32_t addr) {
    asm volatile("ldmatrix.sync.aligned.m8n8.x4.trans.shared.b16 {%0,%1,%2,%3}, [%4];"
        : "=r"(r[0]), "=r"(r[1]), "=r"(r[2]), "=r"(r[3]) : "r"(addr));
}
__device__ __forceinline__ void mma16816(float* c, const uint32_t* a, const uint32_t* b) {
    asm volatile("mma.sync.aligned.m16n8k16.row.col.f32.f16.f16.f32 "
        "{%0,%1,%2,%3}, {%4,%5,%6,%7}, {%8,%9}, {%0,%1,%2,%3};"
        : "+f"(c[0]), "+f"(c[1]), "+f"(c[2]), "+f"(c[3])
        : "r"(a[0]), "r"(a[1]), "r"(a[2]), "r"(a[3]), "r"(b[0]), "r"(b[1]));
}
__device__ __forceinline__ void cp_async16(uint32_t saddr, const void* gaddr) {
    asm volatile("cp.async.cg.shared.global [%0], [%1], 16;"
                 :: "r"(saddr), "l"(gaddr));
}
#define CP_COMMIT() asm volatile("cp.async.commit_group;")
#define CP_WAIT(N)  asm volatile("cp.async.wait_group %0;" :: "n"(N))

// ================= conversion kernels =======================================
__global__ __launch_bounds__(256) void cvt_fp16(
    const float* __restrict__ X, __half* __restrict__ Xh, int n4)
{
    int i = blockIdx.x * 256 + threadIdx.x;
    if (i >= n4) return;
    float4 v = *(const float4*)(X + (size_t)i * 4);
    __half2 a = __floats2half2_rn(v.x, v.y);
    __half2 b = __floats2half2_rn(v.z, v.w);
    uint2 o = make_uint2(*(uint32_t*)&a, *(uint32_t*)&b);
    *(uint2*)(Xh + (size_t)i * 4) = o;
}

// W [K x N] fp32 -> Wt [N x K] fp16
__global__ __launch_bounds__(256) void transpose_h(
    const float* __restrict__ W, __half* __restrict__ Th, int K, int N)
{
    __shared__ float t[32][33];
    int n0 = blockIdx.x * 32, k0 = blockIdx.y * 32;
    int tx = threadIdx.x, ty = threadIdx.y;
#pragma unroll
    for (int i = ty; i < 32; i += 8)
        t[i][tx] = W[(size_t)(k0 + i) * N + n0 + tx];
    __syncthreads();
#pragma unroll
    for (int i = ty; i < 32; i += 8)
        Th[(size_t)(n0 + i) * K + k0 + tx] = __float2half_rn(t[tx][i]);
}

// ================= fp16 warp-MMA GEMM (R15 geometry) ========================
// C = Ah @ Bh^T + bias (opt silu). Block 128x128, 4 warps (warp 64x64),
// K-step 32, 4-stage cp.async ring with 3 loads in flight. 2 CTAs/SM.
#define GT_ROWSTRIDE 80
#define GT_TILE_B    (128 * GT_ROWSTRIDE)     // 10240 B
#define GT_STAGE_B   (2 * GT_TILE_B)          // A, B   = 20480 B
#define GEMM_SMEM    (4 * GT_STAGE_B)         // 81920 B

template<int SILU, int OUTH>
__global__ __launch_bounds__(128, 2) void gemm_mma(
    const __half* __restrict__ Ah, const __half* __restrict__ Bh,
    const float* __restrict__ bias, void* __restrict__ Cv,
    int Ng, int Kg)
{
    extern __shared__ char smem[];
    const uint32_t sb = smem_u32(smem);
    const int tid  = threadIdx.x;
    const int lane = tid & 31;
    const int wid  = tid >> 5;          // 0..3
    const int wm   = wid & 1;           // 2 warps in M
    const int wn   = wid >> 1;          // 2 warps in N
    const int m0 = blockIdx.y * 128;
    const int n0 = blockIdx.x * 128;

    const __half* gsrc[2] = { Ah + (size_t)m0 * Kg, Bh + (size_t)n0 * Kg };

    const int a_row = ((lane >> 3) & 1) * 8 + (lane & 7);
    const int a_kof = (lane >> 4) * 8;
    const int b_row = (lane >> 4) * 8 + (lane & 7);
    const int b_kof = ((lane >> 3) & 1) * 8;

    float acc[4][8][4];
#pragma unroll
    for (int i = 0; i < 4; i++)
#pragma unroll
        for (int j = 0; j < 8; j++)
#pragma unroll
            for (int k = 0; k < 4; k++) acc[i][j][k] = 0.f;

    const int nst = Kg >> 5;

    auto load_stage = [&](int s) {
        const uint32_t stb = sb + (s & 3) * GT_STAGE_B;
        const int k0 = s << 5;
#pragma unroll
        for (int j = 0; j < 8; j++) {
            int c = tid + j * 128;          // 0..1023
            int tile = c >> 9;              // 0..1
            int idx = c & 511;
            int r = idx >> 2, q = idx & 3;
            uint32_t sa = stb + tile * GT_TILE_B + r * GT_ROWSTRIDE + q * 16;
            cp_async16(sa, gsrc[tile] + (size_t)r * Kg + k0 + q * 8);
        }
        CP_COMMIT();
    };

    load_stage(0);
    load_stage(1);
    load_stage(2);

    for (int i = 0; i < nst; i++) {
        CP_WAIT(2);
        __syncthreads();
        if (i + 3 < nst) load_stage(i + 3);

        const uint32_t stb = sb + (i & 3) * GT_STAGE_B;
        const uint32_t sA  = stb;
        const uint32_t sB  = stb + GT_TILE_B;

#pragma unroll
        for (int kk = 0; kk < 2; kk++) {
            const int kb = kk * 16;
            uint32_t ah[4][4], bh[4][4];
#pragma unroll
            for (int mi = 0; mi < 4; mi++) {
                uint32_t ro = (uint32_t)((wm * 64 + mi * 16 + a_row) * GT_ROWSTRIDE
                                         + (kb + a_kof) * 2);
                ldsm4(ah[mi], sA + ro);
            }
#pragma unroll
            for (int nj = 0; nj < 4; nj++) {
                uint32_t ro = (uint32_t)((wn * 64 + nj * 16 + b_row) * GT_ROWSTRIDE
                                         + (kb + b_kof) * 2);
                ldsm4(bh[nj], sB + ro);
            }
#pragma unroll
            for (int mi = 0; mi < 4; mi++)
#pragma unroll
                for (int ni = 0; ni < 8; ni++) {
                    const uint32_t* bf = &bh[ni >> 1][2 * (ni & 1)];
                    mma16816(acc[mi][ni], ah[mi], bf);
                }
        }
        __syncthreads();
    }

    const int g = lane >> 2, t4 = lane & 3;
#pragma unroll
    for (int mi = 0; mi < 4; mi++) {
#pragma unroll
        for (int ni = 0; ni < 8; ni++) {
            int row0 = m0 + wm * 64 + mi * 16 + g;
            int col  = n0 + wn * 64 + ni * 8 + t4 * 2;
            float b0 = bias[col], b1 = bias[col + 1];
            float z0 = acc[mi][ni][0] + b0, z1 = acc[mi][ni][1] + b1;
            float z2 = acc[mi][ni][2] + b0, z3 = acc[mi][ni][3] + b1;
            if (SILU) {
                z0 = z0 / (1.f + expf(-z0)); z1 = z1 / (1.f + expf(-z1));
                z2 = z2 / (1.f + expf(-z2)); z3 = z3 / (1.f + expf(-z3));
            }
            if (OUTH) {
                __half* C = (__half*)Cv;
                *(__half2*)&C[(size_t)row0 * Ng + col] = __floats2half2_rn(z0, z1);
                *(__half2*)&C[(size_t)(row0 + 8) * Ng + col] = __floats2half2_rn(z2, z3);
            } else {
                float* C = (float*)Cv;
                *(float2*)&C[(size_t)row0 * Ng + col]       = make_float2(z0, z1);
                *(float2*)&C[(size_t)(row0 + 8) * Ng + col] = make_float2(z2, z3);
            }
        }
    }
}

// ================= RoPE + head-scatter (fp16 in) ============================
__global__ __launch_bounds__(256) void rope_scatter(
    const float* __restrict__ cosb, const float* __restrict__ sinb,
    const __half* __restrict__ qkv,
    __half* __restrict__ Qh,
    __half* __restrict__ Kh,
    __half* __restrict__ Vh)
{
    __shared__ __half row[6144];
    __shared__ float cr[1024];
    __shared__ float sr[1024];

    const int m = blockIdx.x;
    const int b = m >> 11;
    const int l = m & 2047;
    const __half* src = qkv + (size_t)m * 6144;

    for (int i = threadIdx.x; i < 768; i += 256)
        *(uint4*)&row[i * 8] = *(const uint4*)&src[i * 8];
    {
        int i4 = threadIdx.x;
        *(float4*)&cr[i4 * 4] = *(const float4*)&cosb[(size_t)l * 1024 + i4 * 4];
        *(float4*)&sr[i4 * 4] = *(const float4*)&sinb[(size_t)l * 1024 + i4 * 4];
    }
    __syncthreads();

    const float scale = 0.08838834764831845f;
#pragma unroll
    for (int it = 0; it < 4; it++) {
        int u = it * 256 + threadIdx.x;
        int h = u >> 6;
        int dlo = u & 63;
        int jj = dlo * 16 + h;
        float c = cr[jj], s = sr[jj];
        float q1 = __half2float(row[jj]);
        float q2 = __half2float(row[jj + 1024]);
        float k1 = __half2float(row[2048 + jj]);
        float k2 = __half2float(row[3072 + jj]);
        size_t base = (((size_t)b * 16 + h) * 2048 + l) * 128;

        Qh[base + dlo]      = __float2half_rn(( q1 * c + q2 * s) * scale);
        Qh[base + dlo + 64] = __float2half_rn((-q1 * s + q2 * c) * scale);
        Kh[base + dlo]      = __float2half_rn( k1 * c + k2 * s);
        Kh[base + dlo + 64] = __float2half_rn(-k1 * s + k2 * c);
        Vh[base + dlo]      = row[4096 + jj];
        Vh[base + dlo + 64] = row[4096 + jj + 1024];
    }
}

// ================= causal flash attention (HMMA, pipelined loads) ===========
// Tiles: Q, K0, K1, V (4 x 64x128 padded) = 69632 B -> 3 CTAs/SM.
// K double-buffered (prefetch during compute); V wait deferred past S+softmax.
#define AT_SW 136
#define AT_TILE_H (64 * AT_SW)
#define ATT_SMEM (4 * AT_TILE_H * 2)            // 69632 B

__global__ __launch_bounds__(128) void attn_mma(
    const __half* __restrict__ Qhg,
    const __half* __restrict__ Khg,
    const __half* __restrict__ Vhg,
    __half* __restrict__ Yh)
{
    extern __shared__ __half smh[];
    __half* sQh = smh;
    __half* sK0 = sQh + AT_TILE_H;
    __half* sK1 = sK0 + AT_TILE_H;
    __half* sVh = sK1 + AT_TILE_H;

    const uint32_t uQh = smem_u32(sQh);
    const uint32_t uK[2] = {smem_u32(sK0), smem_u32(sK1)};
    const uint32_t uVh = smem_u32(sVh);

    const int tid = threadIdx.x;
    const int lane = tid & 31;
    const int w = tid >> 5;
    const int g = lane >> 2, t4 = lane & 3;
    const int qt = gridDim.x - 1 - blockIdx.x;     // heavy blocks first
    const int bh = blockIdx.y;
    const int b = bh >> 4, h = bh & 15;
    const int q0 = qt * 64;
    const size_t hb = (size_t)bh * L_ * HD_;

    const int lrow = lane & 15;
    const int lcol8 = ((lane >> 4) << 3);

    const __half* Kg = Khg + hb;
    const __half* Vg = Vhg + hb;

    auto load_k = [&](int kt) {
        const int k0 = kt * 64;
        const uint32_t dst = uK[kt & 1];
#pragma unroll
        for (int j = 0; j < 8; j++) {
            int idx = tid + j * 128;
            int r = idx >> 4, ch = idx & 15;
            cp_async16(dst + (uint32_t)(r * AT_SW + ch * 8) * 2,
                       Kg + (size_t)(k0 + r) * 128 + ch * 8);
        }
    };
    auto load_v = [&](int kt) {
        const int k0 = kt * 64;
#pragma unroll
        for (int j = 0; j < 8; j++) {
            int idx = tid + j * 128;
            int r = idx >> 4, ch = idx & 15;
            cp_async16(uVh + (uint32_t)(r * AT_SW + ch * 8) * 2,
                       Vg + (size_t)(k0 + r) * 128 + ch * 8);
        }
    };

    // ---- prologue: [Q + K(0)] group, then [V(0)] group ----
    {
#pragma unroll
        for (int j = 0; j < 8; j++) {
            int idx = tid + j * 128;
            int r = idx >> 4, ch = idx & 15;
            cp_async16(uQh + (uint32_t)(r * AT_SW + ch * 8) * 2,
                       Qhg + hb + (size_t)(q0 + r) * 128 + ch * 8);
        }
        load_k(0);
        CP_COMMIT();
        load_v(0);
        CP_COMMIT();
    }

    float acc_o[16][4];
#pragma unroll
    for (int j = 0; j < 16; j++)
#pragma unroll
        for (int c = 0; c < 4; c++) acc_o[j][c] = 0.f;
    float mrow[2] = {-1e30f, -1e30f};
    float lrowv[2] = {0.f, 0.f};

    for (int kt = 0; kt <= qt; kt++) {
        // wait: K(kt) ready (V(kt) may still be in flight)
        CP_WAIT(1);
        __syncthreads();
        // prefetch K(kt+1) into the other K buffer
        if (kt < qt) load_k(kt + 1);
        CP_COMMIT();

        const uint32_t uKc = uK[kt & 1];

        // ---- S = Q K^T ----
        float acc_s[8][4];
#pragma unroll
        for (int j = 0; j < 8; j++)
#pragma unroll
            for (int c = 0; c < 4; c++) acc_s[j][c] = 0.f;

#pragma unroll
        for (int ks = 0; ks < 8; ks++) {
            const uint32_t aoff = (uint32_t)((w * 16 + lrow) * AT_SW + ks * 16 + lcol8) * 2;
            uint32_t aQ[4];
            ldsm4(aQ, uQh + aoff);
#pragma unroll
            for (int ng = 0; ng < 4; ng++) {
                const uint32_t boff =
                    (uint32_t)((ng * 16 + lrow) * AT_SW + ks * 16 + lcol8) * 2;
                uint32_t bK[4];
                ldsm4(bK, uKc + boff);
                uint32_t b0[2] = {bK[0], bK[2]}, b1[2] = {bK[1], bK[3]};
                mma16816(acc_s[2 * ng],     aQ, b0);
                mma16816(acc_s[2 * ng + 1], aQ, b1);
            }
        }

        // ---- causal mask on diagonal tile ----
        if (kt == qt) {
#pragma unroll
            for (int j = 0; j < 8; j++)
#pragma unroll
                for (int c = 0; c < 4; c++) {
                    int col = j * 8 + 2 * t4 + (c & 1);
                    int rowr = w * 16 + g + 8 * (c >> 1);
                    if (col > rowr) acc_s[j][c] = -1e30f;
                }
        }

        // ---- online softmax ----
        uint32_t ps[8][2];
#pragma unroll
        for (int rh = 0; rh < 2; rh++) {
            float mx = -1e30f;
#pragma unroll
            for (int j = 0; j < 8; j++)
                mx = fmaxf(mx, fmaxf(acc_s[j][2 * rh], acc_s[j][2 * rh + 1]));
            mx = fmaxf(mx, __shfl_xor_sync(0xffffffffu, mx, 1));
            mx = fmaxf(mx, __shfl_xor_sync(0xffffffffu, mx, 2));
            float mnew = fmaxf(mrow[rh], mx);
            float rs = 0.f;
#pragma unroll
            for (int j = 0; j < 8; j++) {
                float p0 = __expf(acc_s[j][2 * rh]     - mnew);
                float p1 = __expf(acc_s[j][2 * rh + 1] - mnew);
                rs += p0 + p1;
                __half2 hp = __floats2half2_rn(p0, p1);
                ps[j][rh] = *(uint32_t*)&hp;
            }
            rs += __shfl_xor_sync(0xffffffffu, rs, 1);
            rs += __shfl_xor_sync(0xffffffffu, rs, 2);
            float f = __expf(mrow[rh] - mnew);
            lrowv[rh] = lrowv[rh] * f + rs;
            mrow[rh] = mnew;
#pragma unroll
            for (int j = 0; j < 16; j++) {
                acc_o[j][2 * rh]     *= f;
                acc_o[j][2 * rh + 1] *= f;
            }
        }

        // wait: V(kt) ready (K(kt+1) still in flight)
        CP_WAIT(1);
        __syncthreads();

        // ---- O += P V ----
#pragma unroll
        for (int kk = 0; kk < 4; kk++) {
            uint32_t a[4] = {ps[2 * kk][0], ps[2 * kk][1],
                             ps[2 * kk + 1][0], ps[2 * kk + 1][1]};
#pragma unroll
            for (int nd = 0; nd < 8; nd++) {
                const uint32_t voff =
                    (uint32_t)((kk * 16 + lrow) * AT_SW + nd * 16 + lcol8) * 2;
                uint32_t vh[4];
                ldsm4t(vh, uVh + voff);
                mma16816(acc_o[2 * nd],     a, &vh[0]);
                mma16816(acc_o[2 * nd + 1], a, &vh[2]);
            }
        }

        // all warps done with V before next V load overwrites it
        __syncthreads();
        if (kt < qt) load_v(kt + 1);
        CP_COMMIT();
    }

    // ---- epilogue ----
#pragma unroll
    for (int rh = 0; rh < 2; rh++) {
        const int qi = q0 + w * 16 + g + 8 * rh;
        const float inv = 1.f / lrowv[rh];
        const size_t base = ((size_t)(b * L_ + qi)) * H_ + h * HD_;
#pragma unroll
        for (int j = 0; j < 16; j++) {
            __half2 hv = __floats2half2_rn(acc_o[j][2 * rh] * inv,
                                           acc_o[j][2 * rh + 1] * inv);
            *(__half2*)&Yh[base + j * 8 + 2 * t4] = hv;
        }
    }
}

// ================= launch ====================================================
extern "C" void kernel_launch(void* const* d_in, const int* in_sizes, int n_in,
                              void* d_out, int out_size)
{
    (void)in_sizes; (void)n_in; (void)out_size;
    const float* x    = (const float*)d_in[0];
    const float* Wqkv = (const float*)d_in[1];
    const float* bqkv = (const float*)d_in[2];
    const float* Wfc2 = (const float*)d_in[3];
    const float* bfc2 = (const float*)d_in[4];
    const float* cosb = (const float*)d_in[5];
    const float* sinb = (const float*)d_in[6];
    float* out = (float*)d_out;

    __half *qkv_p, *xh, *wqh, *wfh, *yh, *qh, *kh, *vh;
    cudaGetSymbolAddress((void**)&qkv_p, g_qkv);
    cudaGetSymbolAddress((void**)&xh, g_xh);
    cudaGetSymbolAddress((void**)&wqh, g_wq_h);
    cudaGetSymbolAddress((void**)&wfh, g_wf_h);
    cudaGetSymbolAddress((void**)&yh, g_yh);
    cudaGetSymbolAddress((void**)&qh, g_qh);
    cudaGetSymbolAddress((void**)&kh, g_kh);
    cudaGetSymbolAddress((void**)&vh, g_vh);

    cudaFuncSetAttribute(gemm_mma<0, 1>,
                         cudaFuncAttributeMaxDynamicSharedMemorySize, GEMM_SMEM);
    cudaFuncSetAttribute(gemm_mma<1, 0>,
                         cudaFuncAttributeMaxDynamicSharedMemorySize, GEMM_SMEM);
    cudaFuncSetAttribute(attn_mma,
                         cudaFuncAttributeMaxDynamicSharedMemorySize, ATT_SMEM);

    // input conversions
    cvt_fp16<<<(M_ * H_) / 1024, 256>>>(x, xh, (M_ * H_) / 4);
    transpose_h<<<dim3(N1_ / 32, H_ / 32), dim3(32, 8)>>>(Wqkv, wqh, H_, N1_);
    transpose_h<<<dim3(H_ / 32, H_ / 32), dim3(32, 8)>>>(Wfc2, wfh, H_, H_);

    // 1) qkv = x @ Wqkv + bqkv  (fp16 out)
    gemm_mma<0, 1><<<dim3(N1_ / 128, M_ / 128), 128, GEMM_SMEM>>>(
        xh, wqh, bqkv, qkv_p, N1_, H_);
    // 2) RoPE + head scatter
    rope_scatter<<<M_, 256>>>(cosb, sinb, qkv_p, qh, kh, vh);
    // 3) causal flash attention -> yh fp16
    attn_mma<<<dim3(32, 64), 128, ATT_SMEM>>>(qh, kh, vh, yh);
    // 4) out = silu(y @ Wfc2 + bfc2)  (fp32 out)
    gemm_mma<1, 0><<<dim3(H_ / 128, M_ / 128), 128, GEMM_SMEM>>>(
        yh, wfh, bfc2, out, H_, H_);
}